// round 3
// baseline (speedup 1.0000x reference)
// 2-layer GRU (H=32, B=4096, T=512) + 16-dim projection.
// Round 3: register-resident weights + 2-warp software pipeline.
//   warp A (role 0): layer-0 recurrence, weights Wih0/Whh0 in 192 regs.
//   warp B (role 1): layer-1 recurrence, weights Wih1/Whh1 in 192 regs.
//   A runs one timestep ahead; h0 handed via double-buffered shared row,
//   one __syncthreads per step. Hot loop = FFMA2 + broadcast LDS only.
#include <cuda_runtime.h>

#define Hh 32
#define Tt 512
#define Bb 4096
#define NB 2                        // batch elems per warp-pair
#define PAIRS 4                     // warp pairs per block
#define NTHREADS (PAIRS * 2 * 32)   // 256
#define NBLOCKS (Bb / (PAIRS * NB)) // 512

union F2 { float2 f; unsigned long long u; };

__device__ __forceinline__ void fma2(F2& d, F2 a, F2 b) {
    asm("fma.rn.f32x2 %0, %1, %2, %0;" : "+l"(d.u) : "l"(a.u), "l"(b.u));
}
__device__ __forceinline__ float fsig(float x) {
    return 1.0f / (1.0f + __expf(-x));
}
__device__ __forceinline__ float ftanh(float x) {
    return fmaf(2.0f, fsig(2.0f * x), -1.0f);
}

__global__ void __launch_bounds__(NTHREADS, 1) gru_pipe_kernel(
    const float* __restrict__ x,
    const float* __restrict__ Wih0, const float* __restrict__ Whh0,
    const float* __restrict__ bih0, const float* __restrict__ bhh0,
    const float* __restrict__ Wih1, const float* __restrict__ Whh1,
    const float* __restrict__ bih1, const float* __restrict__ bhh1,
    const float* __restrict__ Wproj, const float* __restrict__ bproj,
    float* __restrict__ out)
{
    __shared__ float sbias[2][4][32];            // [layer][r,z,xn,hn][lane]
    __shared__ float xbuf [PAIRS][2][NB][32];
    __shared__ float h0buf[PAIRS][2][NB][32];
    __shared__ float h1buf[PAIRS][2][NB][32];

    const int lane = threadIdx.x & 31;
    const int winb = threadIdx.x >> 5;
    const int pair = winb >> 1;
    const int role = winb & 1;                   // 0 = layer0 (A), 1 = layer1 (B)
    const int b0   = blockIdx.x * (PAIRS * NB) + pair * NB;

    if (winb == 0) {
        sbias[0][0][lane] = bih0[lane]      + bhh0[lane];
        sbias[0][1][lane] = bih0[32 + lane] + bhh0[32 + lane];
        sbias[0][2][lane] = bih0[64 + lane];
        sbias[0][3][lane] = bhh0[64 + lane];
    } else if (winb == 1) {
        sbias[1][0][lane] = bih1[lane]      + bhh1[lane];
        sbias[1][1][lane] = bih1[32 + lane] + bhh1[32 + lane];
        sbias[1][2][lane] = bih1[64 + lane];
        sbias[1][3][lane] = bhh1[64 + lane];
    }

    // ---- this lane's weight rows into registers: wx/wh[g*16+p] = k-pair p of
    // gate g's row (row index g*32+lane), for this warp's layer.
    const float* Wx = role ? Wih1 : Wih0;
    const float* Wh = role ? Whh1 : Whh0;
    F2 wx[48], wh[48];
#pragma unroll
    for (int g = 0; g < 3; g++) {
#pragma unroll
        for (int p = 0; p < 16; p++) {
            wx[g * 16 + p].f = *(const float2*)(Wx + (g * 32 + lane) * 32 + 2 * p);
            wh[g * 16 + p].f = *(const float2*)(Wh + (g * 32 + lane) * 32 + 2 * p);
        }
    }

    // ---- init state / buffers ----
    const float* xp[NB];
    float hcur[NB];
#pragma unroll
    for (int b = 0; b < NB; b++) hcur[b] = 0.0f;

    if (role == 0) {
#pragma unroll
        for (int b = 0; b < NB; b++) {
            xp[b] = x + (size_t)(b0 + b) * (Tt * Hh) + lane;
            xbuf[pair][0][b][lane] = xp[b][0];          // x(0)
            xp[b] += Hh;
            h0buf[pair][1][b][lane] = 0.0f;             // h0(-1) = 0
        }
    } else {
#pragma unroll
        for (int b = 0; b < NB; b++)
            h1buf[pair][1][b][lane] = 0.0f;             // h1(-1) = 0
    }
    __syncthreads();

    const float br  = sbias[role][0][lane];
    const float bz  = sbias[role][1][lane];
    const float bxn = sbias[role][2][lane];
    const float bhn = sbias[role][3][lane];

    for (int i = 0; i <= Tt; i++) {
        const int cur  = i & 1;
        const int prev = cur ^ 1;

        if (role == 0) {
            if (i < Tt) {
                // prefetch x(i+1)
                float xn[NB];
#pragma unroll
                for (int b = 0; b < NB; b++) xn[b] = 0.0f;
                if (i + 1 < Tt) {
#pragma unroll
                    for (int b = 0; b < NB; b++) { xn[b] = xp[b][0]; xp[b] += Hh; }
                }
                float hnew[NB];
#pragma unroll
                for (int b = 0; b < NB; b++) {
                    F2 ar, az, axn, ahn;
                    ar.f.x  = br;  ar.f.y  = 0.0f;
                    az.f.x  = bz;  az.f.y  = 0.0f;
                    axn.f.x = bxn; axn.f.y = 0.0f;
                    ahn.f.x = bhn; ahn.f.y = 0.0f;
                    const float* vx = &xbuf [pair][cur ][b][0];
                    const float* vh = &h0buf[pair][prev][b][0];
#pragma unroll
                    for (int q = 0; q < 8; q++) {
                        const float4 v4 = *(const float4*)(vx + 4 * q);
                        F2 vl, vh2;
                        vl.f.x = v4.x;  vl.f.y = v4.y;
                        vh2.f.x = v4.z; vh2.f.y = v4.w;
                        fma2(ar,  vl, wx[      2 * q]); fma2(ar,  vh2, wx[      2 * q + 1]);
                        fma2(az,  vl, wx[16  + 2 * q]); fma2(az,  vh2, wx[16  + 2 * q + 1]);
                        fma2(axn, vl, wx[32  + 2 * q]); fma2(axn, vh2, wx[32  + 2 * q + 1]);
                    }
#pragma unroll
                    for (int q = 0; q < 8; q++) {
                        const float4 v4 = *(const float4*)(vh + 4 * q);
                        F2 vl, vh2;
                        vl.f.x = v4.x;  vl.f.y = v4.y;
                        vh2.f.x = v4.z; vh2.f.y = v4.w;
                        fma2(ar,  vl, wh[      2 * q]); fma2(ar,  vh2, wh[      2 * q + 1]);
                        fma2(az,  vl, wh[16  + 2 * q]); fma2(az,  vh2, wh[16  + 2 * q + 1]);
                        fma2(ahn, vl, wh[32  + 2 * q]); fma2(ahn, vh2, wh[32  + 2 * q + 1]);
                    }
                    const float r  = fsig(ar.f.x + ar.f.y);
                    const float z  = fsig(az.f.x + az.f.y);
                    const float nn = ftanh(fmaf(r, ahn.f.x + ahn.f.y,
                                                   axn.f.x + axn.f.y));
                    hnew[b] = fmaf(z, hcur[b] - nn, nn);
                }
                __syncwarp();   // all lanes finished reading xbuf[cur]/h0buf[prev]
#pragma unroll
                for (int b = 0; b < NB; b++) {
                    h0buf[pair][cur][b][lane] = hnew[b];
                    hcur[b] = hnew[b];
                    if (i + 1 < Tt) xbuf[pair][prev][b][lane] = xn[b];  // (i+1)&1 == prev
                }
            }
        } else {
            if (i >= 1) {
                // compute h1(i-1): input = h0(i-1) in h0buf[prev], own hist in h1buf[cur]
                float hnew[NB];
#pragma unroll
                for (int b = 0; b < NB; b++) {
                    F2 ar, az, axn, ahn;
                    ar.f.x  = br;  ar.f.y  = 0.0f;
                    az.f.x  = bz;  az.f.y  = 0.0f;
                    axn.f.x = bxn; axn.f.y = 0.0f;
                    ahn.f.x = bhn; ahn.f.y = 0.0f;
                    const float* vx = &h0buf[pair][prev][b][0];
                    const float* vh = &h1buf[pair][cur ][b][0];   // h1(i-2)
#pragma unroll
                    for (int q = 0; q < 8; q++) {
                        const float4 v4 = *(const float4*)(vx + 4 * q);
                        F2 vl, vh2;
                        vl.f.x = v4.x;  vl.f.y = v4.y;
                        vh2.f.x = v4.z; vh2.f.y = v4.w;
                        fma2(ar,  vl, wx[      2 * q]); fma2(ar,  vh2, wx[      2 * q + 1]);
                        fma2(az,  vl, wx[16  + 2 * q]); fma2(az,  vh2, wx[16  + 2 * q + 1]);
                        fma2(axn, vl, wx[32  + 2 * q]); fma2(axn, vh2, wx[32  + 2 * q + 1]);
                    }
#pragma unroll
                    for (int q = 0; q < 8; q++) {
                        const float4 v4 = *(const float4*)(vh + 4 * q);
                        F2 vl, vh2;
                        vl.f.x = v4.x;  vl.f.y = v4.y;
                        vh2.f.x = v4.z; vh2.f.y = v4.w;
                        fma2(ar,  vl, wh[      2 * q]); fma2(ar,  vh2, wh[      2 * q + 1]);
                        fma2(az,  vl, wh[16  + 2 * q]); fma2(az,  vh2, wh[16  + 2 * q + 1]);
                        fma2(ahn, vl, wh[32  + 2 * q]); fma2(ahn, vh2, wh[32  + 2 * q + 1]);
                    }
                    const float r  = fsig(ar.f.x + ar.f.y);
                    const float z  = fsig(az.f.x + az.f.y);
                    const float nn = ftanh(fmaf(r, ahn.f.x + ahn.f.y,
                                                   axn.f.x + axn.f.y));
                    hnew[b] = fmaf(z, hcur[b] - nn, nn);
                }
                __syncwarp();   // all lanes finished reading h1buf[cur]
#pragma unroll
                for (int b = 0; b < NB; b++) {
                    h1buf[pair][prev][b][lane] = hnew[b];   // (i-1)&1 == prev
                    hcur[b] = hnew[b];
                }
            }
        }
        __syncthreads();
    }

    // ---- projection (layer-1 warps hold final h1 in hcur) ----
    if (role == 1) {
#pragma unroll
        for (int b = 0; b < NB; b++) {
            float acc = (lane < 16) ? bproj[lane] : 0.0f;
#pragma unroll
            for (int k = 0; k < 32; k++) {
                const float v = __shfl_sync(0xffffffffu, hcur[b], k);
                if (lane < 16) acc = fmaf(v, Wproj[lane * 32 + k], acc);
            }
            if (lane < 16) out[(b0 + b) * 16 + lane] = acc;
        }
    }
}

extern "C" void kernel_launch(void* const* d_in, const int* in_sizes, int n_in,
                              void* d_out, int out_size)
{
    const float* x     = (const float*)d_in[0];
    const float* Wih0  = (const float*)d_in[1];
    const float* Whh0  = (const float*)d_in[2];
    const float* bih0  = (const float*)d_in[3];
    const float* bhh0  = (const float*)d_in[4];
    const float* Wih1  = (const float*)d_in[5];
    const float* Whh1  = (const float*)d_in[6];
    const float* bih1  = (const float*)d_in[7];
    const float* bhh1  = (const float*)d_in[8];
    const float* Wproj = (const float*)d_in[9];
    const float* bproj = (const float*)d_in[10];
    float* out = (float*)d_out;

    gru_pipe_kernel<<<NBLOCKS, NTHREADS>>>(
        x, Wih0, Whh0, bih0, bhh0, Wih1, Whh1, bih1, bhh1, Wproj, bproj, out);
}